// round 4
// baseline (speedup 1.0000x reference)
#include <cuda_runtime.h>

#define DIMC 384
#define NP 49
#define HW 112
#define CH_STRIDE (112 * 112)

__global__ void __launch_bounds__(384) attn_ds_kernel(
    const float* __restrict__ hr,   // (8, 384, 112, 112)
    const float* __restrict__ du,   // (8, 16, 16, 1)
    const float* __restrict__ aw,   // (384,)
    const float* __restrict__ ab,   // (1,)
    const float* __restrict__ wt,   // (7,7) -> 49
    const float* __restrict__ bt,   // (7,7) -> 49
    float* __restrict__ out)        // (8, 384, 16, 16)
{
    extern __shared__ float patch[];          // [384][49], pitch 49 floats
    __shared__ float s_logits[NP];
    __shared__ float s_attn[NP];

    const int tid  = threadIdx.x;             // 0..383
    const int lane = tid & 31;
    const int wid  = tid >> 5;                // 0..11
    const int blk  = blockIdx.x;              // b*256 + h*16 + w
    const int b    = blk >> 8;
    const int h    = (blk >> 4) & 15;
    const int wcol = blk & 15;

    // Patch origin: rows [h*7, h*7+7), cols [w*7, w*7+7)  (stride==K: exact tiling)
    const float* src = hr + (size_t)b * DIMC * CH_STRIDE + (h * 7) * HW + (wcol * 7);

    // ---- Phase 1: load full 49x384 patch into SMEM, layout [c*49 + p] ----
    // idx = tid + it*384 is linear -> STS write-linear (conflict-free), LDG
    // covers 7-float contiguous row segments. Divisions replaced by verified
    // magic multiplies; 7-wide explicit batches force >=7 outstanding LDGs.
    //   c  = idx/49  == (idx*42800)>>21      (exact for idx < 43690)
    //   py = p/7     == (p*9363)>>16         (exact for p < 49)
    //   py*HW + px   == p + 105*py
    #pragma unroll
    for (int itb = 0; itb < 7; ++itb) {
        float v[7];
        #pragma unroll
        for (int j = 0; j < 7; ++j) {
            unsigned idx = (unsigned)tid + (unsigned)(itb * 7 + j) * 384u;
            unsigned c   = (idx * 42800u) >> 21;
            unsigned p   = idx - c * 49u;
            unsigned py  = (p * 9363u) >> 16;
            v[j] = __ldg(&src[(size_t)c * CH_STRIDE + p + 105u * py]);
        }
        #pragma unroll
        for (int j = 0; j < 7; ++j)
            patch[tid + (itb * 7 + j) * 384] = v[j];
    }
    __syncthreads();

    // ---- Phase 2: logits[p] = sum_c patch[c][p] * aw[c]  (+ ab) ----
    // Lane addresses c*49+p with c distinct mod 32 -> bank (17c+p)%32 is a
    // bijection -> conflict-free. aw[] read via LDG (L1-resident after first).
    for (int p = wid; p < NP; p += 12) {
        float acc = 0.0f;
        #pragma unroll
        for (int k = 0; k < 12; ++k) {
            int c = lane + k * 32;
            acc = fmaf(patch[c * NP + p], __ldg(&aw[c]), acc);
        }
        #pragma unroll
        for (int o = 16; o > 0; o >>= 1)
            acc += __shfl_xor_sync(0xffffffffu, acc, o);
        if (lane == 0) s_logits[p] = acc + __ldg(&ab[0]);
    }
    __syncthreads();

    // ---- Phase 3: masked affine + softmax over 49 (warp 0) ----
    if (wid == 0) {
        const float m = (__ldg(&du[blk]) > 0.2f) ? 1.0f : 0.0f;  // scalar mask
        const int p1 = lane + 32;
        float l0 = s_logits[lane] * m * __ldg(&wt[lane]) + __ldg(&bt[lane]);
        float l1 = (p1 < NP) ? (s_logits[p1] * m * __ldg(&wt[p1]) + __ldg(&bt[p1]))
                             : -1e30f;
        float mx = fmaxf(l0, l1);
        #pragma unroll
        for (int o = 16; o > 0; o >>= 1)
            mx = fmaxf(mx, __shfl_xor_sync(0xffffffffu, mx, o));
        float e0 = __expf(l0 - mx);
        float e1 = (p1 < NP) ? __expf(l1 - mx) : 0.0f;
        float s = e0 + e1;
        #pragma unroll
        for (int o = 16; o > 0; o >>= 1)
            s += __shfl_xor_sync(0xffffffffu, s, o);
        const float inv = 1.0f / s;
        s_attn[lane] = e0 * inv;
        if (p1 < NP) s_attn[p1] = e1 * inv;
    }
    __syncthreads();

    // ---- Phase 4: out[c] = sum_p patch[c][p] * attn[p] ----
    // Thread tid == channel c. Lane banks (17c+p)%32 distinct -> conflict-free.
    float acc = 0.0f;
    #pragma unroll
    for (int p = 0; p < NP; ++p)
        acc = fmaf(patch[tid * NP + p], s_attn[p], acc);

    // out[b][c][h][w]; sectors completed by the 15 sibling-w CTAs in L2.
    out[((size_t)b * DIMC + tid) * 256 + h * 16 + wcol] = acc;
}

extern "C" void kernel_launch(void* const* d_in, const int* in_sizes, int n_in,
                              void* d_out, int out_size)
{
    const float* hr = (const float*)d_in[0];  // hr_feats
    // d_in[1] = guidance (unused, zeros)
    const float* du = (const float*)d_in[2];  // dropout_u
    const float* aw = (const float*)d_in[3];
    const float* ab = (const float*)d_in[4];
    const float* wt = (const float*)d_in[5];
    const float* bt = (const float*)d_in[6];
    float* out = (float*)d_out;

    const size_t smem = (size_t)DIMC * NP * sizeof(float);  // 75264 B dynamic
    cudaFuncSetAttribute(attn_ds_kernel,
                         cudaFuncAttributeMaxDynamicSharedMemorySize, (int)smem);
    // Ask for the full 228KB carveout so 3 CTAs/SM can fit (75.3KB + ~0.4KB
    // static + 1KB reserved per CTA).
    cudaFuncSetAttribute(attn_ds_kernel,
                         cudaFuncAttributePreferredSharedMemoryCarveout, 100);
    attn_ds_kernel<<<2048, 384, smem>>>(hr, du, aw, ab, wt, bt, out);
}

// round 6
// speedup vs baseline: 1.5886x; 1.5886x over previous
#include <cuda_runtime.h>

#define DIMC 384
#define NP 49
#define HW 112
#define CH_STRIDE (112 * 112)

__global__ void __launch_bounds__(384, 2) attn_ds_kernel(
    const float* __restrict__ hr,   // (8, 384, 112, 112)
    const float* __restrict__ du,   // (8, 16, 16, 1)
    const float* __restrict__ aw,   // (384,)
    const float* __restrict__ ab,   // (1,)
    const float* __restrict__ wt,   // (7,7) -> 49
    const float* __restrict__ bt,   // (7,7) -> 49
    float* __restrict__ out)        // (8, 384, 16, 16)
{
    extern __shared__ float patch[];          // [384][49], pitch 49 floats
    __shared__ float s_aw[DIMC];
    __shared__ float s_logits[NP];
    __shared__ float s_attn[NP];

    const int tid  = threadIdx.x;             // 0..383
    const int lane = tid & 31;
    const int wid  = tid >> 5;                // 0..11
    const int blk  = blockIdx.x;              // b*256 + h*16 + w
    const int b    = blk >> 8;
    const int h    = (blk >> 4) & 15;
    const int wcol = blk & 15;

    // Patch origin: rows [h*7, h*7+7), cols [w*7, w*7+7)  (stride==K: exact tiling)
    const float* src = hr + (size_t)b * DIMC * CH_STRIDE + (h * 7) * HW + (wcol * 7);

    s_aw[tid] = aw[tid];                      // exactly 384 threads

    // ---- Phase 1: load full 49x384 patch into SMEM, layout [c*49 + p] ----
    // idx = tid + it*384 is linear -> STS write-linear (conflict-free), LDG
    // covers 7-float contiguous row segments. Magic-multiply address math:
    //   c  = idx/49  == (idx*42800)>>21   (exact for idx < 2.1e6)
    //   py = p/7     == (p*9363)>>16      (exact for p < 91750)
    //   py*HW + px   == p + 105*py
    // 7 batches of 7 loads each; __launch_bounds__(384,2) gives reg headroom
    // so all 7 LDGs per batch stay in flight (MLP >= 7 per warp).
    #pragma unroll
    for (int itb = 0; itb < 7; ++itb) {
        float v[7];
        #pragma unroll
        for (int j = 0; j < 7; ++j) {
            unsigned idx = (unsigned)tid + (unsigned)(itb * 7 + j) * 384u;
            unsigned c   = (idx * 42800u) >> 21;
            unsigned p   = idx - c * 49u;
            unsigned py  = (p * 9363u) >> 16;
            v[j] = src[(size_t)c * CH_STRIDE + p + 105u * py];
        }
        #pragma unroll
        for (int j = 0; j < 7; ++j)
            patch[tid + (itb * 7 + j) * 384] = v[j];
    }
    __syncthreads();

    // ---- Phase 2: logits[p] = sum_c patch[c][p] * aw[c]  (+ ab) ----
    // Lane addresses c*49+p with c distinct mod 32 -> bank (17c+p)%32 is a
    // bijection -> conflict-free. aw from SMEM.
    for (int p = wid; p < NP; p += 12) {
        float acc0 = 0.0f, acc1 = 0.0f;
        #pragma unroll
        for (int k = 0; k < 12; k += 2) {
            int c0 = lane + k * 32;
            int c1 = lane + (k + 1) * 32;
            acc0 = fmaf(patch[c0 * NP + p], s_aw[c0], acc0);
            acc1 = fmaf(patch[c1 * NP + p], s_aw[c1], acc1);
        }
        float acc = acc0 + acc1;
        #pragma unroll
        for (int o = 16; o > 0; o >>= 1)
            acc += __shfl_xor_sync(0xffffffffu, acc, o);
        if (lane == 0) s_logits[p] = acc + ab[0];
    }
    __syncthreads();

    // ---- Phase 3: masked affine + softmax over 49 (warp 0) ----
    if (wid == 0) {
        const float m = (du[blk] > 0.2f) ? 1.0f : 0.0f;   // scalar mask per block
        const int p1 = lane + 32;
        float l0 = s_logits[lane] * m * wt[lane] + bt[lane];
        float l1 = (p1 < NP) ? (s_logits[p1] * m * wt[p1] + bt[p1]) : -1e30f;
        float mx = fmaxf(l0, l1);
        #pragma unroll
        for (int o = 16; o > 0; o >>= 1)
            mx = fmaxf(mx, __shfl_xor_sync(0xffffffffu, mx, o));
        float e0 = __expf(l0 - mx);
        float e1 = (p1 < NP) ? __expf(l1 - mx) : 0.0f;
        float s = e0 + e1;
        #pragma unroll
        for (int o = 16; o > 0; o >>= 1)
            s += __shfl_xor_sync(0xffffffffu, s, o);
        const float inv = 1.0f / s;
        s_attn[lane] = e0 * inv;
        if (p1 < NP) s_attn[p1] = e1 * inv;
    }
    __syncthreads();

    // ---- Phase 4: out[c] = sum_p patch[c][p] * attn[p] ----
    // Thread tid == channel c; two accumulators halve the FMA dependence chain.
    float a0 = 0.0f, a1 = 0.0f;
    #pragma unroll
    for (int p = 0; p < 48; p += 2) {
        a0 = fmaf(patch[tid * NP + p],     s_attn[p],     a0);
        a1 = fmaf(patch[tid * NP + p + 1], s_attn[p + 1], a1);
    }
    a0 = fmaf(patch[tid * NP + 48], s_attn[48], a0);

    // out[b][c][h][w]; .cg store keeps the zero-reuse output out of L1,
    // sectors completed by the 15 sibling-w CTAs while resident in L2.
    __stcg(&out[((size_t)b * DIMC + tid) * 256 + h * 16 + wcol], a0 + a1);
}

extern "C" void kernel_launch(void* const* d_in, const int* in_sizes, int n_in,
                              void* d_out, int out_size)
{
    const float* hr = (const float*)d_in[0];  // hr_feats
    // d_in[1] = guidance (unused, zeros)
    const float* du = (const float*)d_in[2];  // dropout_u
    const float* aw = (const float*)d_in[3];
    const float* ab = (const float*)d_in[4];
    const float* wt = (const float*)d_in[5];
    const float* bt = (const float*)d_in[6];
    float* out = (float*)d_out;

    const size_t smem = (size_t)DIMC * NP * sizeof(float);  // 75264 B dynamic
    cudaFuncSetAttribute(attn_ds_kernel,
                         cudaFuncAttributeMaxDynamicSharedMemorySize, (int)smem);
    // NOTE: default L1/smem carveout on purpose — forcing 100 starved L1D
    // and regressed R4 (110us). 2 CTAs/SM with healthy L1 is the sweet spot.
    attn_ds_kernel<<<2048, 384, smem>>>(hr, du, aw, ab, wt, bt, out);
}